// round 12
// baseline (speedup 1.0000x reference)
#include <cuda_runtime.h>
#include <cuda_bf16.h>
#include <cstdint>

#define M_DIM 8192
#define N_DIM 4096
#define K_DIM 4096

// ---------------- scratch (device globals; no allocations allowed) ----------
// A packed as [K/16][M/16] tiles of 512B: 16x16 bf16 tile in m16n8k16 A-frag order.
// B packed as [K/16][N/8]  tiles of 256B: 16x8  bf16 tile in m16n8k16 B-frag order.
__device__ __align__(128) __nv_bfloat16 g_A[(size_t)M_DIM * K_DIM];
__device__ __align__(128) __nv_bfloat16 g_B[(size_t)N_DIM * K_DIM];
__device__ float g_sa[M_DIM];   // activation scale per token
__device__ float g_sw[N_DIM];   // weight scale per row

// ---------------- helpers ----------------------------------------------------
__device__ __forceinline__ uint32_t smem_u32(const void* p) {
    uint32_t a;
    asm("{ .reg .u64 t; cvta.to.shared.u64 t, %1; cvt.u32.u64 %0, t; }"
        : "=r"(a) : "l"(p));
    return a;
}

#define CP_ASYNC16(dst, src) \
    asm volatile("cp.async.cg.shared.global [%0], [%1], 16;" \
                 :: "r"(dst), "l"(src) : "memory")
#define CP_COMMIT() asm volatile("cp.async.commit_group;" ::: "memory")
#define CP_WAIT0()  asm volatile("cp.async.wait_group 0;" ::: "memory")

__device__ __forceinline__ void mma_bf16(float* d, const unsigned* a, const unsigned* b) {
    asm volatile(
        "mma.sync.aligned.m16n8k16.row.col.f32.bf16.bf16.f32 "
        "{%0,%1,%2,%3}, {%4,%5,%6,%7}, {%8,%9}, {%0,%1,%2,%3};"
        : "+f"(d[0]), "+f"(d[1]), "+f"(d[2]), "+f"(d[3])
        : "r"(a[0]), "r"(a[1]), "r"(a[2]), "r"(a[3]),
          "r"(b[0]), "r"(b[1]));
}

// ---------------- fused quantization + fragment packing ----------------------
// A elem (m,k): tile=(k>>4)*(M/16)+(m>>4); r=m&15,c=k&15;
//   lane=(r&7)*4+((c&7)>>1); reg=(r>=8)+2*(c>=8); byte=lane*16+reg*4+(c&1)*2
// B elem (n,k): tile=(k>>4)*(N/8)+(n>>3); g=n&7,kk=k&15;
//   lane=g*4+((kk&7)>>1); reg=(kk>=8); byte=lane*8+reg*4+(kk&1)*2
__device__ __forceinline__ void do_quant_x(const float* __restrict__ x, int m, int tid) {
    const float4* xr = (const float4*)(x + (size_t)m * K_DIM);
    float4 v[4];
    float mn = 3.4e38f, mx = -3.4e38f;
#pragma unroll
    for (int i = 0; i < 4; i++) {
        v[i] = xr[tid + i * 256];
        mn = fminf(mn, fminf(fminf(v[i].x, v[i].y), fminf(v[i].z, v[i].w)));
        mx = fmaxf(mx, fmaxf(fmaxf(v[i].x, v[i].y), fmaxf(v[i].z, v[i].w)));
    }
#pragma unroll
    for (int o = 16; o; o >>= 1) {
        mn = fminf(mn, __shfl_xor_sync(0xFFFFFFFFu, mn, o));
        mx = fmaxf(mx, __shfl_xor_sync(0xFFFFFFFFu, mx, o));
    }
    __shared__ float smn[8], smx[8];
    if ((tid & 31) == 0) { smn[tid >> 5] = mn; smx[tid >> 5] = mx; }
    __syncthreads();
    mn = smn[0]; mx = smx[0];
#pragma unroll
    for (int i = 1; i < 8; i++) { mn = fminf(mn, smn[i]); mx = fmaxf(mx, smx[i]); }

    float rng = mx - mn;
    float scale = (rng > 0.0f) ? rng * (1.0f / 255.0f) : 1.0f;
    float zpf = rintf(-mn / scale);
    if (tid == 0) g_sa[m] = scale;

    const int r = m & 15, mt = m >> 4;
    const uint32_t lr = (uint32_t)(r & 7) * 4;
    const uint32_t rhi = (r >= 8) ? 4u : 0u;
    float inv = 1.0f / scale;
    char* Ab = (char*)g_A;
#pragma unroll
    for (int i = 0; i < 4; i++) {
        int f = tid + i * 256;
        int kt = f >> 2;                 // k16 index
        int c = (f * 4) & 15;            // 0,4,8,12
        float q0 = fminf(fmaxf(rintf(v[i].x * inv) + zpf, 0.0f), 255.0f) - zpf;
        float q1 = fminf(fmaxf(rintf(v[i].y * inv) + zpf, 0.0f), 255.0f) - zpf;
        float q2 = fminf(fmaxf(rintf(v[i].z * inv) + zpf, 0.0f), 255.0f) - zpf;
        float q3 = fminf(fmaxf(rintf(v[i].w * inv) + zpf, 0.0f), 255.0f) - zpf;
        size_t tile = ((size_t)kt * (M_DIM / 16) + mt) * 512;
        uint32_t lane0 = lr + ((c & 7) >> 1);
        uint32_t off0 = lane0 * 16 + rhi + ((c >= 8) ? 8u : 0u);
        *(__nv_bfloat162*)(Ab + tile + off0) = __floats2bfloat162_rn(q0, q1);
        int c2 = c + 2;
        uint32_t lane1 = lr + ((c2 & 7) >> 1);
        uint32_t off1 = lane1 * 16 + rhi + ((c2 >= 8) ? 8u : 0u);
        *(__nv_bfloat162*)(Ab + tile + off1) = __floats2bfloat162_rn(q2, q3);
    }
}

__device__ __forceinline__ void do_quant_w(const float* __restrict__ w, int n, int tid) {
    const float4* wr = (const float4*)(w + (size_t)n * K_DIM);
    float4 v[4];
    float am = 0.0f;
#pragma unroll
    for (int i = 0; i < 4; i++) {
        v[i] = wr[tid + i * 256];
        am = fmaxf(am, fmaxf(fmaxf(fabsf(v[i].x), fabsf(v[i].y)),
                             fmaxf(fabsf(v[i].z), fabsf(v[i].w))));
    }
#pragma unroll
    for (int o = 16; o; o >>= 1)
        am = fmaxf(am, __shfl_xor_sync(0xFFFFFFFFu, am, o));
    __shared__ float sam[8];
    if ((tid & 31) == 0) sam[tid >> 5] = am;
    __syncthreads();
    am = sam[0];
#pragma unroll
    for (int i = 1; i < 8; i++) am = fmaxf(am, sam[i]);

    float scale = (am > 0.0f) ? am * (1.0f / 127.0f) : 1.0f;
    float inv = 1.0f / scale;
    if (tid == 0) g_sw[n] = scale;

    const int g = n & 7, nt = n >> 3;
    const uint32_t lg = (uint32_t)g * 4;
    char* Bb = (char*)g_B;
#pragma unroll
    for (int i = 0; i < 4; i++) {
        int f = tid + i * 256;
        int kt = f >> 2;
        int kk = (f * 4) & 15;           // 0,4,8,12
        float q0 = fminf(fmaxf(rintf(v[i].x * inv), -127.0f), 127.0f);
        float q1 = fminf(fmaxf(rintf(v[i].y * inv), -127.0f), 127.0f);
        float q2 = fminf(fmaxf(rintf(v[i].z * inv), -127.0f), 127.0f);
        float q3 = fminf(fmaxf(rintf(v[i].w * inv), -127.0f), 127.0f);
        size_t tile = ((size_t)kt * (N_DIM / 8) + nt) * 256;
        uint32_t lane0 = lg + ((kk & 7) >> 1);
        uint32_t off0 = lane0 * 8 + ((kk >= 8) ? 4u : 0u);
        *(__nv_bfloat162*)(Bb + tile + off0) = __floats2bfloat162_rn(q0, q1);
        int k2 = kk + 2;
        uint32_t lane1 = lg + ((k2 & 7) >> 1);
        uint32_t off1 = lane1 * 8 + ((k2 >= 8) ? 4u : 0u);
        *(__nv_bfloat162*)(Bb + tile + off1) = __floats2bfloat162_rn(q2, q3);
    }
}

__global__ __launch_bounds__(256) void quant_kernel(const float* __restrict__ x,
                                                    const float* __restrict__ w) {
    int bid = blockIdx.x;
    if (bid < M_DIM) do_quant_x(x, bid, threadIdx.x);
    else             do_quant_w(w, bid - M_DIM, threadIdx.x);
}

// ---- GEMM: bf16 HMMA, 128x256 CTA, 8 warps of 64x64, BK=128, 2-stage -------
// Fragment double-buffering: chunk kk+1's LDS issued before chunk kk's MMAs.
#define BM 128
#define BN 256
#define K16_PER_STAGE 8                 // BK = 128 bf16
#define KSTAGES (K_DIM / (16 * K16_PER_STAGE))   // 32
#define STAGE_BYTES 98304               // A 32KB + B 64KB
#define SA_OFF(s) ((s) * STAGE_BYTES)
#define SB_OFF(s) ((s) * STAGE_BYTES + 32768)
#define SMEM_BYTES (2 * STAGE_BYTES)    // 192 KB

__global__ __launch_bounds__(256, 1)
void gemm_kernel(const float* __restrict__ bias, float* __restrict__ out) {
    extern __shared__ unsigned char smem[];
    const int tid = threadIdx.x;
    const int wid = tid >> 5, lid = tid & 31;
    const int wm = wid >> 2, wn = wid & 3;        // 2 x 4 warp grid, 64x64 tiles
    const int m0 = blockIdx.y * BM;
    const int n0 = blockIdx.x * BN;
    const int mtBase = m0 >> 4;
    const int ntBase = n0 >> 3;
    const uint32_t sbase = smem_u32(smem);
    const char* Ab = (const char*)g_A;
    const char* Bb = (const char*)g_B;

    const uint32_t my16 = (uint32_t)tid * 16;
    const uint32_t afro = (uint32_t)(wm * 4) * 512 + (uint32_t)lid * 16;
    const uint32_t bfro = (uint32_t)(wn * 8) * 256 + (uint32_t)lid * 8;

    float acc[4][8][4];
#pragma unroll
    for (int i = 0; i < 4; i++)
#pragma unroll
        for (int j = 0; j < 8; j++)
#pragma unroll
            for (int q = 0; q < 4; q++) acc[i][j][q] = 0.0f;

#define ISSUE_CHUNK(STG, S, KKC)                                                 \
    do {                                                                         \
        int k16 = (STG) * K16_PER_STAGE + (KKC);                                 \
        size_t at = ((size_t)k16 * (M_DIM / 16) + mtBase) * 512;                 \
        CP_ASYNC16(sbase + SA_OFF(S) + (KKC) * 4096 + my16, Ab + at + my16);     \
        size_t bt = ((size_t)k16 * (N_DIM / 8) + ntBase) * 256;                  \
        CP_ASYNC16(sbase + SB_OFF(S) + (KKC) * 8192 + my16, Bb + bt + my16);     \
        CP_ASYNC16(sbase + SB_OFF(S) + (KKC) * 8192 + 4096 + my16,               \
                   Bb + bt + 4096 + my16);                                       \
    } while (0)

#define LOAD_FRAG(BUF, KKC)                                                      \
    do {                                                                         \
        _Pragma("unroll")                                                        \
        for (int i = 0; i < 4; i++)                                              \
            af[BUF][i] = *(const uint4*)(sA + (KKC) * 4096 + afro + i * 512);    \
        _Pragma("unroll")                                                        \
        for (int j = 0; j < 8; j++)                                              \
            bf[BUF][j] = *(const uint2*)(sB + (KKC) * 8192 + bfro + j * 256);    \
    } while (0)

    // prologue: stage 0 fully
#pragma unroll
    for (int kk = 0; kk < K16_PER_STAGE; kk++) ISSUE_CHUNK(0, 0, kk);
    CP_COMMIT();

    uint4 af[2][4];
    uint2 bf[2][8];

    int sread = 0;
#pragma unroll 1
    for (int st = 0; st < KSTAGES; st++) {
        CP_WAIT0();               // stage st resident (sole outstanding group)
        __syncthreads();

        const unsigned char* sA = smem + SA_OFF(sread);
        const unsigned char* sB = smem + SB_OFF(sread);
        const int swrite = sread ^ 1;
        const bool pf = (st + 1 < KSTAGES);

        LOAD_FRAG(0, 0);          // chunk 0 fill (exposed)

#pragma unroll
        for (int kk = 0; kk < K16_PER_STAGE; kk++) {
            const int cur = kk & 1, nxt = cur ^ 1;
            // prefetch chunk kk+1 fragments before chunk kk's MMAs
            if (kk + 1 < K16_PER_STAGE) LOAD_FRAG(nxt, kk + 1);
            // interleave next-stage gmem loads (front-loaded, first 4 chunks)
            if (pf && kk < 4) {
                ISSUE_CHUNK(st + 1, swrite, 2 * kk);
                ISSUE_CHUNK(st + 1, swrite, 2 * kk + 1);
            }
#pragma unroll
            for (int i = 0; i < 4; i++)
#pragma unroll
                for (int j = 0; j < 8; j++)
                    mma_bf16(acc[i][j], (const unsigned*)&af[cur][i],
                             (const unsigned*)&bf[cur][j]);
        }
        CP_COMMIT();
        sread ^= 1;
    }

    // ---------------- epilogue: dequant + bias --------------------------------
    const int g = lid >> 2, tig = lid & 3;
#pragma unroll
    for (int i = 0; i < 4; i++) {
        int r0 = m0 + wm * 64 + i * 16 + g;
        int r1 = r0 + 8;
        float sa0 = g_sa[r0], sa1 = g_sa[r1];
#pragma unroll
        for (int j = 0; j < 8; j++) {
            int col = n0 + wn * 64 + j * 8 + tig * 2;
            float sw0 = g_sw[col], sw1 = g_sw[col + 1];
            float b0 = bias[col], b1 = bias[col + 1];
            float2 y0, y1;
            y0.x = acc[i][j][0] * (sa0 * sw0) + b0;
            y0.y = acc[i][j][1] * (sa0 * sw1) + b1;
            y1.x = acc[i][j][2] * (sa1 * sw0) + b0;
            y1.y = acc[i][j][3] * (sa1 * sw1) + b1;
            *(float2*)(out + (size_t)r0 * N_DIM + col) = y0;
            *(float2*)(out + (size_t)r1 * N_DIM + col) = y1;
        }
    }
}

// ---------------- launch -----------------------------------------------------
extern "C" void kernel_launch(void* const* d_in, const int* in_sizes, int n_in,
                              void* d_out, int out_size) {
    const float* x = (const float*)d_in[0];
    const float* w = (const float*)d_in[1];
    const float* bias = (const float*)d_in[2];
    float* out = (float*)d_out;

    cudaFuncSetAttribute(gemm_kernel, cudaFuncAttributeMaxDynamicSharedMemorySize,
                         SMEM_BYTES);

    quant_kernel<<<M_DIM + N_DIM, 256>>>(x, w);
    dim3 grid(N_DIM / BN, M_DIM / BM);
    gemm_kernel<<<grid, 256, SMEM_BYTES>>>(bias, out);
}